// round 12
// baseline (speedup 1.0000x reference)
#include <cuda_runtime.h>
#include <cuda_fp16.h>
#include <cstdint>

// ---------------------------------------------------------------------------
// Problem constants
// ---------------------------------------------------------------------------
#define N_TOK   4096
#define DIM     4096
#define OUT_DIM 4096
#define NE      8
#define NH      3
#define NR      16
#define NU      384
#define K_ALL   (DIM + NU)     // 4480
#define SCALE_F 2.0f
#define NWG     256            // padded prep-weight rows
#define KSLICES 8

// Scratch (static). Rows are K-major fp16 with a permutation inside each
// 32-element k-group: pos(k) = ((k>>1)&3)*8 + ((k>>3)&3)*2 + (k&1)
__device__ __half g_Xh[(size_t)N_TOK * K_ALL];           // [N][4480] rn(x) | rn(u)
__device__ __half g_Wh[(size_t)OUT_DIM * K_ALL];         // [O][4480] rn([baseW;Bfl]^T)
__device__ __half g_Wgh[(size_t)NWG * DIM];              // [256][4096] gathered A,R
__device__ float  g_P4[(size_t)KSLICES * N_TOK * NWG];   // split-K partials (fp32)
__device__ float  g_L [(size_t)N_TOK * NE];              // exact fp32 router logits

__device__ __forceinline__ int hperm32(int k) {
    return ((k >> 1) & 3) * 8 + ((k >> 3) & 3) * 2 + (k & 1);
}
__device__ __forceinline__ int hperm_inv(int p) {
    return (p & 1) + 2 * (p >> 3) + 8 * ((p >> 1) & 1) + 16 * ((p >> 2) & 1);
}

// ---------------------------------------------------------------------------
// K1: Xh[:, 0:4096] = rn_f16(x), permuted. One thread per 32-k chunk.
// ---------------------------------------------------------------------------
__global__ __launch_bounds__(256) void round_x_kernel(const float* __restrict__ x) {
    size_t id  = (size_t)blockIdx.x * blockDim.x + threadIdx.x;   // N*128 total
    size_t row = id >> 7;
    size_t ch  = id & 127;
    const float* src = x + row * DIM + ch * 32;
    float4 v[8];
    #pragma unroll
    for (int q = 0; q < 8; q++) v[q] = reinterpret_cast<const float4*>(src)[q];
    __align__(16) __half tmp[32];
    #pragma unroll
    for (int p = 0; p < 32; p++) {
        int k = hperm_inv(p);                         // compile-time
        tmp[p] = __float2half_rn((&v[k >> 2].x)[k & 3]);
    }
    uint4* dst = reinterpret_cast<uint4*>(g_Xh + row * K_ALL + ch * 32);
    const uint4* tp = reinterpret_cast<const uint4*>(tmp);
    #pragma unroll
    for (int q = 0; q < 4; q++) dst[q] = tp[q];
}

// ---------------------------------------------------------------------------
// K2: Wh[n][perm(k)] = rn_f16([baseW;Bfl]^T). Tile K=128 x N=64, smem-staged.
// ---------------------------------------------------------------------------
__global__ __launch_bounds__(256) void transpose_w_kernel(
    const float* __restrict__ baseW, const float* __restrict__ Bfl) {
    __shared__ float st[128][66];
    const int tid = threadIdx.x;
    const int kb = blockIdx.x * 128, nb = blockIdx.y * 64;

    const bool isB = (kb >= DIM);
    const float* src = isB ? (Bfl + (size_t)(kb - DIM) * OUT_DIM + nb)
                           : (baseW + (size_t)kb * OUT_DIM + nb);
    #pragma unroll
    for (int i = 0; i < 8; i++) {
        int idx = i * 256 + tid;            // 0..2047
        int k = idx >> 4, q = idx & 15;
        float4 v = *reinterpret_cast<const float4*>(src + (size_t)k * OUT_DIM + q * 4);
        st[k][q * 4 + 0] = v.x;
        st[k][q * 4 + 1] = v.y;
        st[k][q * 4 + 2] = v.z;
        st[k][q * 4 + 3] = v.w;
    }
    __syncthreads();

    const int n = tid & 63;
    const int c = tid >> 6;                  // 0..3
    __align__(16) __half tmp[32];
    #pragma unroll
    for (int j = 0; j < 32; j++)
        tmp[hperm32(j)] = __float2half_rn(st[c * 32 + j][n]);
    uint4* dst = reinterpret_cast<uint4*>(
        g_Wh + (size_t)(nb + n) * K_ALL + kb + c * 32);
    const uint4* tp = reinterpret_cast<const uint4*>(tmp);
    #pragma unroll
    for (int q = 0; q < 4; q++) dst[q] = tp[q];
}

// ---------------------------------------------------------------------------
// K3: gather Wgh (permuted): rows 0..127 = A[e][:,r], 128..151 = Rm[e][:,h].
// ---------------------------------------------------------------------------
__global__ __launch_bounds__(256) void gather_wg_kernel(
    const float* __restrict__ A, const float* __restrict__ Rm) {
    int idx = blockIdx.x * 256 + threadIdx.x;   // NWG * 128 total
    int j = idx >> 7, gd = idx & 127;
    int d0 = gd * 32;
    __align__(16) __half tmp[32];
    if (j < 128) {
        int e = j >> 4, rr = j & 15;
        const float* base = A + (size_t)e * DIM * NR + rr;
        #pragma unroll
        for (int d = 0; d < 32; d++)
            tmp[hperm32(d)] = __float2half_rn(base[(size_t)(d0 + d) * NR]);
    } else if (j < 152) {
        int jj = j - 128, e = jj / 3, h = jj - 3 * e;
        const float* base = Rm + (size_t)e * DIM * NH + h;
        #pragma unroll
        for (int d = 0; d < 32; d++)
            tmp[hperm32(d)] = __float2half_rn(base[(size_t)(d0 + d) * NH]);
    } else {
        #pragma unroll
        for (int d = 0; d < 32; d++) tmp[d] = __float2half_rn(0.f);
    }
    uint4* dst = reinterpret_cast<uint4*>(g_Wgh + (size_t)j * DIM + d0);
    const uint4* tp = reinterpret_cast<const uint4*>(tmp);
    #pragma unroll
    for (int q = 0; q < 4; q++) dst[q] = tp[q];
}

// ---------------------------------------------------------------------------
// K4: FP16 tensor GEMM (fp32 accum)  out (+)= A[M][lda] @ B[N][ldb]^T.
// 128x128 CTA, 2x2 warps (64x64), BK=64, 3-stage cp.async, 2 CTAs/SM.
// accum=1: read-modify-write epilogue (for the K=384 delta pass).
// ---------------------------------------------------------------------------
#define BM 128
#define BN 128
#define BKH 64
#define NSTAGE 3
#define ASTG (BM * 128)        // 16 KB
#define BSTG (BN * 128)        // 16 KB
#define SMEM_GEMM (NSTAGE * (ASTG + BSTG))   // 96 KB
#define NTHR 128

__device__ __forceinline__ void cp16(uint32_t daddr, const void* gptr) {
    asm volatile("cp.async.cg.shared.global [%0], [%1], 16;"
                 :: "r"(daddr), "l"(gptr) : "memory");
}
__device__ __forceinline__ uint4 lds128(uint32_t a) {
    uint4 v;
    asm volatile("ld.shared.v4.b32 {%0,%1,%2,%3}, [%4];"
                 : "=r"(v.x), "=r"(v.y), "=r"(v.z), "=r"(v.w) : "r"(a));
    return v;
}
__device__ __forceinline__ uint32_t smem_u32(const void* p) {
    uint32_t a;
    asm("{ .reg .u64 t; cvta.to.shared.u64 t, %1; cvt.u32.u64 %0, t; }" : "=r"(a) : "l"(p));
    return a;
}
__device__ __forceinline__ uint32_t swz(uint32_t v) {
    return ((v & 1u) << 2) | (v >> 1);
}
__device__ __forceinline__ void mma16(float* c, uint32_t a0, uint32_t a1,
                                      uint32_t a2, uint32_t a3,
                                      uint32_t b0, uint32_t b1) {
    asm("mma.sync.aligned.m16n8k16.row.col.f32.f16.f16.f32 "
        "{%0,%1,%2,%3}, {%4,%5,%6,%7}, {%8,%9}, {%0,%1,%2,%3};\n"
        : "+f"(c[0]), "+f"(c[1]), "+f"(c[2]), "+f"(c[3])
        : "r"(a0), "r"(a1), "r"(a2), "r"(a3), "r"(b0), "r"(b1));
}

__global__ __launch_bounds__(NTHR, 2) void mma_gemm_kernel(
    const __half* __restrict__ Ag, int lda,
    const __half* __restrict__ Bg, int ldb,
    float* __restrict__ out, int ldo, int ksteps,
    size_t slice_k, size_t out_slice, int accum)
{
    extern __shared__ __align__(1024) char sm[];
    const uint32_t smuA = smem_u32(sm);
    const uint32_t smuB = smuA + NSTAGE * ASTG;

    Ag  += (size_t)blockIdx.z * slice_k;
    Bg  += (size_t)blockIdx.z * slice_k;
    out += (size_t)blockIdx.z * out_slice;

    const int tid = threadIdx.x, lane = tid & 31, warp = tid >> 5;
    const int wm = warp & 1, wn = warp >> 1;
    const int g = lane >> 2, tg = lane & 3;
    const int m0 = blockIdx.y * BM, n0 = blockIdx.x * BN;

    const int lrow = tid >> 3;
    const int lkq  = tid & 7;
    const uint32_t sgr = (lkq ^ swz(lrow & 7)) * 16;

    float c[4][8][4];
    #pragma unroll
    for (int i = 0; i < 4; i++)
        #pragma unroll
        for (int j = 0; j < 8; j++)
            #pragma unroll
            for (int k = 0; k < 4; k++) c[i][j][k] = 0.f;

    auto issue = [&](int kt, int s) {
        const __half* ab = Ag + (size_t)(m0 + lrow) * lda + (size_t)kt * BKH + lkq * 8;
        const __half* bb = Bg + (size_t)(n0 + lrow) * ldb + (size_t)kt * BKH + lkq * 8;
        #pragma unroll
        for (int i = 0; i < 8; i++)
            cp16(smuA + s * ASTG + (lrow + 16 * i) * 128 + sgr,
                 ab + (size_t)(16 * i) * lda);
        #pragma unroll
        for (int i = 0; i < 8; i++)
            cp16(smuB + s * BSTG + (lrow + 16 * i) * 128 + sgr,
                 bb + (size_t)(16 * i) * ldb);
    };

    #pragma unroll
    for (int s = 0; s < NSTAGE - 1; s++) {
        issue(s, s);
        asm volatile("cp.async.commit_group;" ::: "memory");
    }

    const uint32_t fsw = swz((uint32_t)g) * 16;

    for (int kt = 0; kt < ksteps; kt++) {
        const int cur = kt % NSTAGE;
        asm volatile("cp.async.wait_group %0;" :: "n"(NSTAGE - 2) : "memory");
        __syncthreads();

        int nk = kt + NSTAGE - 1;
        if (nk < ksteps) issue(nk, nk % NSTAGE);
        asm volatile("cp.async.commit_group;" ::: "memory");

        const uint32_t sA = smuA + cur * ASTG + (wm * 64 + g) * 128;
        const uint32_t sB = smuB + cur * BSTG + (wn * 64 + g) * 128;

        #pragma unroll
        for (int chk = 0; chk < 2; chk++) {
            const uint32_t goff = ((chk * 4 + tg) * 16) ^ fsw;
            uint4 alo[4], ahi[4], bv[8];
            #pragma unroll
            for (int im = 0; im < 4; im++) {
                uint32_t ra = sA + im * 16 * 128 + goff;
                alo[im] = lds128(ra);
                ahi[im] = lds128(ra + 8 * 128);
            }
            #pragma unroll
            for (int in = 0; in < 8; in++)
                bv[in] = lds128(sB + in * 8 * 128 + goff);

            #pragma unroll
            for (int im = 0; im < 4; im++)
                #pragma unroll
                for (int in = 0; in < 8; in++) {
                    mma16(c[im][in], alo[im].x, ahi[im].x, alo[im].y, ahi[im].y,
                          bv[in].x, bv[in].y);
                    mma16(c[im][in], alo[im].z, ahi[im].z, alo[im].w, ahi[im].w,
                          bv[in].z, bv[in].w);
                }
        }
    }

    #pragma unroll
    for (int im = 0; im < 4; im++) {
        int row = m0 + wm * 64 + im * 16 + g;
        #pragma unroll
        for (int in = 0; in < 8; in++) {
            int col = n0 + wn * 64 + in * 8 + 2 * tg;
            float2* p0 = reinterpret_cast<float2*>(&out[(size_t)row * ldo + col]);
            float2* p1 = reinterpret_cast<float2*>(&out[(size_t)(row + 8) * ldo + col]);
            float2 v0 = make_float2(c[im][in][0], c[im][in][1]);
            float2 v1 = make_float2(c[im][in][2], c[im][in][3]);
            if (accum) {
                float2 o0 = *p0, o1 = *p1;
                v0.x += o0.x; v0.y += o0.y;
                v1.x += o1.x; v1.y += o1.y;
            }
            *p0 = v0;
            *p1 = v1;
        }
    }
}

// ---------------------------------------------------------------------------
// K5: exact fp32 router logits  g_L = x @ routerW^T (side stream).
// ---------------------------------------------------------------------------
__global__ __launch_bounds__(512) void router_kernel(
    const float* __restrict__ x, const float* __restrict__ routerW)
{
    extern __shared__ float rw[];               // [NE * DIM] = 128KB
    const int tid = threadIdx.x, lane = tid & 31, warp = tid >> 5;
    const int token = blockIdx.x * 16 + warp;

    for (int i = tid; i < NE * DIM / 4; i += 512)
        reinterpret_cast<float4*>(rw)[i] = reinterpret_cast<const float4*>(routerW)[i];
    __syncthreads();

    const float4* xr  = reinterpret_cast<const float4*>(x + (size_t)token * DIM);
    const float4* rwv = reinterpret_cast<const float4*>(rw);

    float acc[NE];
    #pragma unroll
    for (int e = 0; e < NE; e++) acc[e] = 0.f;

    #pragma unroll 4
    for (int t = 0; t < 32; t++) {
        int i4 = lane + 32 * t;
        float4 xv = __ldg(xr + i4);
        #pragma unroll
        for (int e = 0; e < NE; e++) {
            float4 w = rwv[e * (DIM / 4) + i4];
            acc[e] += xv.x * w.x + xv.y * w.y + xv.z * w.z + xv.w * w.w;
        }
    }
    #pragma unroll
    for (int e = 0; e < NE; e++)
        #pragma unroll
        for (int o = 16; o > 0; o >>= 1)
            acc[e] += __shfl_xor_sync(0xffffffffu, acc[e], o);

    if (lane == 0) {
        #pragma unroll
        for (int e = 0; e < NE; e++)
            g_L[(size_t)token * NE + e] = acc[e];
    }
}

// ---------------------------------------------------------------------------
// K6: finalize — reduce split-K partials, top-2 gates from g_L, head softmax,
// u -> Xh[:, 4096:] (permuted). 8 tokens / block, 256 threads.
// ---------------------------------------------------------------------------
__global__ __launch_bounds__(256) void finalize_kernel()
{
    __shared__ float sP[8][160];
    __shared__ float scoeff[8][24];

    const int tid = threadIdx.x, lane = tid & 31, warp = tid >> 5;
    const int token = blockIdx.x * 8 + warp;

    #pragma unroll
    for (int rep = 0; rep < 5; rep++) {
        int idx = lane + 32 * rep;
        float s = 0.f;
        #pragma unroll
        for (int sl = 0; sl < KSLICES; sl++)
            s += g_P4[((size_t)sl * N_TOK + token) * NWG + idx];
        sP[warp][idx] = s;
    }
    __syncwarp();

    if (lane == 0) {
        float acc[NE];
        #pragma unroll
        for (int e = 0; e < NE; e++) acc[e] = g_L[(size_t)token * NE + e];

        int i1 = 0;
        #pragma unroll
        for (int e = 1; e < NE; e++) if (acc[e] > acc[i1]) i1 = e;
        int i2 = (i1 == 0) ? 1 : 0;
        #pragma unroll
        for (int e = 0; e < NE; e++)
            if (e != i1 && acc[e] > acc[i2]) i2 = e;

        float ed = expf(acc[i2] - acc[i1]);
        float g1 = 1.f / (1.f + ed);
        float g2 = ed / (1.f + ed);

        #pragma unroll
        for (int q = 0; q < 24; q++) scoeff[warp][q] = 0.f;

        int   ids[2] = {i1, i2};
        float gs[2]  = {g1, g2};
        #pragma unroll
        for (int p = 0; p < 2; p++) {
            int e = ids[p];
            float h0 = sP[warp][128 + e * 3 + 0];
            float h1 = sP[warp][128 + e * 3 + 1];
            float h2 = sP[warp][128 + e * 3 + 2];
            float m  = fmaxf(h0, fmaxf(h1, h2));
            float x0 = expf(h0 - m), x1 = expf(h1 - m), x2 = expf(h2 - m);
            float inv = gs[p] * SCALE_F / (x0 + x1 + x2);
            scoeff[warp][e * 3 + 0] = x0 * inv;
            scoeff[warp][e * 3 + 1] = x1 * inv;
            scoeff[warp][e * 3 + 2] = x2 * inv;
        }
    }
    __syncwarp();

    #pragma unroll
    for (int rep = 0; rep < NU / 32; rep++) {
        int j = lane + 32 * rep;
        int e = j / 48;
        int jr = j - e * 48;
        int h = jr >> 4, r = jr & 15;
        float u = scoeff[warp][e * 3 + h] * sP[warp][e * 16 + r];
        g_Xh[(size_t)token * K_ALL + DIM + (j & ~31) + hperm32(j & 31)] =
            __float2half_rn(u);
    }
}

// ---------------------------------------------------------------------------
// host launch — split main GEMM: the K=4096 x-part starts immediately after
// round_x/transpose; the whole prep chain (router, gather, prep GEMM,
// finalize) runs CONCURRENTLY on a side stream; a K=384 accumulate GEMM
// applies the LoRA delta at the end.
// ---------------------------------------------------------------------------
extern "C" void kernel_launch(void* const* d_in, const int* in_sizes, int n_in,
                              void* d_out, int out_size) {
    const float* x       = (const float*)d_in[0];
    const float* baseW   = (const float*)d_in[1];
    const float* routerW = (const float*)d_in[2];
    const float* A       = (const float*)d_in[3];
    const float* B       = (const float*)d_in[4];
    const float* Rm      = (const float*)d_in[5];
    float* out = (float*)d_out;

    void *pXh = nullptr, *pWh = nullptr, *pWgh = nullptr, *pP4 = nullptr;
    cudaGetSymbolAddress(&pXh,  g_Xh);
    cudaGetSymbolAddress(&pWh,  g_Wh);
    cudaGetSymbolAddress(&pWgh, g_Wgh);
    cudaGetSymbolAddress(&pP4,  g_P4);

    static bool init_done = false;
    static cudaStream_t s1, s2;
    static cudaEvent_t evRoot, evW, evX, evU;
    if (!init_done) {
        cudaFuncSetAttribute(mma_gemm_kernel,
                             cudaFuncAttributeMaxDynamicSharedMemorySize, SMEM_GEMM);
        cudaFuncSetAttribute(router_kernel,
                             cudaFuncAttributeMaxDynamicSharedMemorySize,
                             NE * DIM * sizeof(float));
        cudaStreamCreateWithFlags(&s1, cudaStreamNonBlocking);
        cudaStreamCreateWithFlags(&s2, cudaStreamNonBlocking);
        cudaEventCreateWithFlags(&evRoot, cudaEventDisableTiming);
        cudaEventCreateWithFlags(&evW,    cudaEventDisableTiming);
        cudaEventCreateWithFlags(&evX,    cudaEventDisableTiming);
        cudaEventCreateWithFlags(&evU,    cudaEventDisableTiming);
        init_done = true;
    }

    // fork side streams
    cudaEventRecord(evRoot, 0);
    cudaStreamWaitEvent(s1, evRoot, 0);
    cudaStreamWaitEvent(s2, evRoot, 0);

    // s1: W transpose (needed by the big GEMM)
    transpose_w_kernel<<<dim3(K_ALL / 128, OUT_DIM / 64), 256, 0, s1>>>(baseW, B);
    cudaEventRecord(evW, s1);

    // main: round x (needed by both GEMM paths)
    round_x_kernel<<<(N_TOK * 128) / 256, 256>>>(x);
    cudaEventRecord(evX, 0);

    // s2: full prep chain, concurrent with the big GEMM
    router_kernel<<<N_TOK / 16, 512, NE * DIM * sizeof(float), s2>>>(x, routerW);
    gather_wg_kernel<<<(NWG * 128) / 256, 256, 0, s2>>>(A, Rm);
    cudaStreamWaitEvent(s2, evX, 0);
    {
        int stages = DIM / BKH / KSLICES;                 // 8
        size_t slice_k = (size_t)stages * BKH;            // 512 halves
        mma_gemm_kernel<<<dim3(NWG / BN, N_TOK / BM, KSLICES), NTHR, SMEM_GEMM, s2>>>(
            (const __half*)pXh, K_ALL, (const __half*)pWgh, DIM,
            (float*)pP4, NWG, stages, slice_k, (size_t)N_TOK * NWG, 0);
    }
    finalize_kernel<<<N_TOK / 8, 256, 0, s2>>>();
    cudaEventRecord(evU, s2);

    // main: big GEMM over the x-part (K = 4096)
    cudaStreamWaitEvent(0, evW, 0);
    mma_gemm_kernel<<<dim3(OUT_DIM / BN, N_TOK / BM, 1), NTHR, SMEM_GEMM>>>(
        (const __half*)pXh, K_ALL, (const __half*)pWh, K_ALL,
        out, OUT_DIM, DIM / BKH, 0, 0, 0);

    // main: LoRA delta GEMM (K = 384), accumulating into out
    cudaStreamWaitEvent(0, evU, 0);
    mma_gemm_kernel<<<dim3(OUT_DIM / BN, N_TOK / BM, 1), NTHR, SMEM_GEMM>>>(
        (const __half*)pXh + DIM, K_ALL, (const __half*)pWh + DIM, K_ALL,
        out, OUT_DIM, NU / BKH, 0, 0, 1);
}

// round 13
// speedup vs baseline: 1.0682x; 1.0682x over previous
#include <cuda_runtime.h>
#include <cuda_fp16.h>
#include <cstdint>

// ---------------------------------------------------------------------------
// Problem constants
// ---------------------------------------------------------------------------
#define N_TOK   4096
#define DIM     4096
#define OUT_DIM 4096
#define NE      8
#define NH      3
#define NR      16
#define NU      384
#define K_ALL   (DIM + NU)     // 4480
#define SCALE_F 2.0f
#define NWG     256            // padded prep-weight rows
#define KSLICES 4              // prep GEMM split-K: 256 CTAs = one wave

// Scratch (static). Rows are K-major fp16 with a permutation inside each
// 32-element k-group: pos(k) = ((k>>1)&3)*8 + ((k>>3)&3)*2 + (k&1)
__device__ __half g_Xh[(size_t)N_TOK * K_ALL];           // [N][4480] rn(x) | rn(u)
__device__ __half g_Wh[(size_t)OUT_DIM * K_ALL];         // [O][4480] rn([baseW;Bfl]^T)
__device__ __half g_Wgh[(size_t)NWG * DIM];              // [256][4096] gathered A,R
__device__ float  g_P4[(size_t)KSLICES * N_TOK * NWG];   // split-K partials (fp32)
__device__ float  g_L [(size_t)N_TOK * NE];              // exact fp32 router logits

__device__ __forceinline__ int hperm32(int k) {
    return ((k >> 1) & 3) * 8 + ((k >> 3) & 3) * 2 + (k & 1);
}
__device__ __forceinline__ int hperm_inv(int p) {
    return (p & 1) + 2 * (p >> 3) + 8 * ((p >> 1) & 1) + 16 * ((p >> 2) & 1);
}

// ---------------------------------------------------------------------------
// K1: Xh[:, 0:4096] = rn_f16(x), permuted. One thread per 32-k chunk.
// ---------------------------------------------------------------------------
__global__ __launch_bounds__(256) void round_x_kernel(const float* __restrict__ x) {
    size_t id  = (size_t)blockIdx.x * blockDim.x + threadIdx.x;   // N*128 total
    size_t row = id >> 7;
    size_t ch  = id & 127;
    const float* src = x + row * DIM + ch * 32;
    float4 v[8];
    #pragma unroll
    for (int q = 0; q < 8; q++) v[q] = reinterpret_cast<const float4*>(src)[q];
    __align__(16) __half tmp[32];
    #pragma unroll
    for (int p = 0; p < 32; p++) {
        int k = hperm_inv(p);                         // compile-time
        tmp[p] = __float2half_rn((&v[k >> 2].x)[k & 3]);
    }
    uint4* dst = reinterpret_cast<uint4*>(g_Xh + row * K_ALL + ch * 32);
    const uint4* tp = reinterpret_cast<const uint4*>(tmp);
    #pragma unroll
    for (int q = 0; q < 4; q++) dst[q] = tp[q];
}

// ---------------------------------------------------------------------------
// K2: Wh[n][perm(k)] = rn_f16([baseW;Bfl]^T). Tile K=128 x N=64, smem-staged.
// ---------------------------------------------------------------------------
__global__ __launch_bounds__(256) void transpose_w_kernel(
    const float* __restrict__ baseW, const float* __restrict__ Bfl) {
    __shared__ float st[128][66];
    const int tid = threadIdx.x;
    const int kb = blockIdx.x * 128, nb = blockIdx.y * 64;

    const bool isB = (kb >= DIM);
    const float* src = isB ? (Bfl + (size_t)(kb - DIM) * OUT_DIM + nb)
                           : (baseW + (size_t)kb * OUT_DIM + nb);
    #pragma unroll
    for (int i = 0; i < 8; i++) {
        int idx = i * 256 + tid;            // 0..2047
        int k = idx >> 4, q = idx & 15;
        float4 v = *reinterpret_cast<const float4*>(src + (size_t)k * OUT_DIM + q * 4);
        st[k][q * 4 + 0] = v.x;
        st[k][q * 4 + 1] = v.y;
        st[k][q * 4 + 2] = v.z;
        st[k][q * 4 + 3] = v.w;
    }
    __syncthreads();

    const int n = tid & 63;
    const int c = tid >> 6;                  // 0..3
    __align__(16) __half tmp[32];
    #pragma unroll
    for (int j = 0; j < 32; j++)
        tmp[hperm32(j)] = __float2half_rn(st[c * 32 + j][n]);
    uint4* dst = reinterpret_cast<uint4*>(
        g_Wh + (size_t)(nb + n) * K_ALL + kb + c * 32);
    const uint4* tp = reinterpret_cast<const uint4*>(tmp);
    #pragma unroll
    for (int q = 0; q < 4; q++) dst[q] = tp[q];
}

// ---------------------------------------------------------------------------
// K3: gather Wgh (permuted): rows 0..127 = A[e][:,r], 128..151 = Rm[e][:,h].
// ---------------------------------------------------------------------------
__global__ __launch_bounds__(256) void gather_wg_kernel(
    const float* __restrict__ A, const float* __restrict__ Rm) {
    int idx = blockIdx.x * 256 + threadIdx.x;   // NWG * 128 total
    int j = idx >> 7, gd = idx & 127;
    int d0 = gd * 32;
    __align__(16) __half tmp[32];
    if (j < 128) {
        int e = j >> 4, rr = j & 15;
        const float* base = A + (size_t)e * DIM * NR + rr;
        #pragma unroll
        for (int d = 0; d < 32; d++)
            tmp[hperm32(d)] = __float2half_rn(base[(size_t)(d0 + d) * NR]);
    } else if (j < 152) {
        int jj = j - 128, e = jj / 3, h = jj - 3 * e;
        const float* base = Rm + (size_t)e * DIM * NH + h;
        #pragma unroll
        for (int d = 0; d < 32; d++)
            tmp[hperm32(d)] = __float2half_rn(base[(size_t)(d0 + d) * NH]);
    } else {
        #pragma unroll
        for (int d = 0; d < 32; d++) tmp[d] = __float2half_rn(0.f);
    }
    uint4* dst = reinterpret_cast<uint4*>(g_Wgh + (size_t)j * DIM + d0);
    const uint4* tp = reinterpret_cast<const uint4*>(tmp);
    #pragma unroll
    for (int q = 0; q < 4; q++) dst[q] = tp[q];
}

// ---------------------------------------------------------------------------
// K4: FP16 tensor GEMM (fp32 accum)  out = A[M][lda] @ B[N][ldb]^T.
// 128x128 CTA, 2x2 warps (64x64), BK=64, 3-stage cp.async, 2 CTAs/SM.
// ---------------------------------------------------------------------------
#define BM 128
#define BN 128
#define BKH 64
#define NSTAGE 3
#define ASTG (BM * 128)        // 16 KB
#define BSTG (BN * 128)        // 16 KB
#define SMEM_GEMM (NSTAGE * (ASTG + BSTG))   // 96 KB
#define NTHR 128

__device__ __forceinline__ void cp16(uint32_t daddr, const void* gptr) {
    asm volatile("cp.async.cg.shared.global [%0], [%1], 16;"
                 :: "r"(daddr), "l"(gptr) : "memory");
}
__device__ __forceinline__ uint4 lds128(uint32_t a) {
    uint4 v;
    asm volatile("ld.shared.v4.b32 {%0,%1,%2,%3}, [%4];"
                 : "=r"(v.x), "=r"(v.y), "=r"(v.z), "=r"(v.w) : "r"(a));
    return v;
}
__device__ __forceinline__ uint32_t smem_u32(const void* p) {
    uint32_t a;
    asm("{ .reg .u64 t; cvta.to.shared.u64 t, %1; cvt.u32.u64 %0, t; }" : "=r"(a) : "l"(p));
    return a;
}
__device__ __forceinline__ uint32_t swz(uint32_t v) {
    return ((v & 1u) << 2) | (v >> 1);
}
__device__ __forceinline__ void mma16(float* c, uint32_t a0, uint32_t a1,
                                      uint32_t a2, uint32_t a3,
                                      uint32_t b0, uint32_t b1) {
    asm("mma.sync.aligned.m16n8k16.row.col.f32.f16.f16.f32 "
        "{%0,%1,%2,%3}, {%4,%5,%6,%7}, {%8,%9}, {%0,%1,%2,%3};\n"
        : "+f"(c[0]), "+f"(c[1]), "+f"(c[2]), "+f"(c[3])
        : "r"(a0), "r"(a1), "r"(a2), "r"(a3), "r"(b0), "r"(b1));
}

__global__ __launch_bounds__(NTHR, 2) void mma_gemm_kernel(
    const __half* __restrict__ Ag, int lda,
    const __half* __restrict__ Bg, int ldb,
    float* __restrict__ out, int ldo, int ksteps,
    size_t slice_k, size_t out_slice)
{
    extern __shared__ __align__(1024) char sm[];
    const uint32_t smuA = smem_u32(sm);
    const uint32_t smuB = smuA + NSTAGE * ASTG;

    Ag  += (size_t)blockIdx.z * slice_k;
    Bg  += (size_t)blockIdx.z * slice_k;
    out += (size_t)blockIdx.z * out_slice;

    const int tid = threadIdx.x, lane = tid & 31, warp = tid >> 5;
    const int wm = warp & 1, wn = warp >> 1;
    const int g = lane >> 2, tg = lane & 3;
    const int m0 = blockIdx.y * BM, n0 = blockIdx.x * BN;

    const int lrow = tid >> 3;
    const int lkq  = tid & 7;
    const uint32_t sgr = (lkq ^ swz(lrow & 7)) * 16;

    float c[4][8][4];
    #pragma unroll
    for (int i = 0; i < 4; i++)
        #pragma unroll
        for (int j = 0; j < 8; j++)
            #pragma unroll
            for (int k = 0; k < 4; k++) c[i][j][k] = 0.f;

    auto issue = [&](int kt, int s) {
        const __half* ab = Ag + (size_t)(m0 + lrow) * lda + (size_t)kt * BKH + lkq * 8;
        const __half* bb = Bg + (size_t)(n0 + lrow) * ldb + (size_t)kt * BKH + lkq * 8;
        #pragma unroll
        for (int i = 0; i < 8; i++)
            cp16(smuA + s * ASTG + (lrow + 16 * i) * 128 + sgr,
                 ab + (size_t)(16 * i) * lda);
        #pragma unroll
        for (int i = 0; i < 8; i++)
            cp16(smuB + s * BSTG + (lrow + 16 * i) * 128 + sgr,
                 bb + (size_t)(16 * i) * ldb);
    };

    #pragma unroll
    for (int s = 0; s < NSTAGE - 1; s++) {
        issue(s, s);
        asm volatile("cp.async.commit_group;" ::: "memory");
    }

    const uint32_t fsw = swz((uint32_t)g) * 16;

    for (int kt = 0; kt < ksteps; kt++) {
        const int cur = kt % NSTAGE;
        asm volatile("cp.async.wait_group %0;" :: "n"(NSTAGE - 2) : "memory");
        __syncthreads();

        int nk = kt + NSTAGE - 1;
        if (nk < ksteps) issue(nk, nk % NSTAGE);
        asm volatile("cp.async.commit_group;" ::: "memory");

        const uint32_t sA = smuA + cur * ASTG + (wm * 64 + g) * 128;
        const uint32_t sB = smuB + cur * BSTG + (wn * 64 + g) * 128;

        #pragma unroll
        for (int chk = 0; chk < 2; chk++) {
            const uint32_t goff = ((chk * 4 + tg) * 16) ^ fsw;
            uint4 alo[4], ahi[4], bv[8];
            #pragma unroll
            for (int im = 0; im < 4; im++) {
                uint32_t ra = sA + im * 16 * 128 + goff;
                alo[im] = lds128(ra);
                ahi[im] = lds128(ra + 8 * 128);
            }
            #pragma unroll
            for (int in = 0; in < 8; in++)
                bv[in] = lds128(sB + in * 8 * 128 + goff);

            #pragma unroll
            for (int im = 0; im < 4; im++)
                #pragma unroll
                for (int in = 0; in < 8; in++) {
                    mma16(c[im][in], alo[im].x, ahi[im].x, alo[im].y, ahi[im].y,
                          bv[in].x, bv[in].y);
                    mma16(c[im][in], alo[im].z, ahi[im].z, alo[im].w, ahi[im].w,
                          bv[in].z, bv[in].w);
                }
        }
    }

    #pragma unroll
    for (int im = 0; im < 4; im++) {
        int row = m0 + wm * 64 + im * 16 + g;
        #pragma unroll
        for (int in = 0; in < 8; in++) {
            int col = n0 + wn * 64 + in * 8 + 2 * tg;
            float2 v0 = make_float2(c[im][in][0], c[im][in][1]);
            float2 v1 = make_float2(c[im][in][2], c[im][in][3]);
            *reinterpret_cast<float2*>(&out[(size_t)row * ldo + col])       = v0;
            *reinterpret_cast<float2*>(&out[(size_t)(row + 8) * ldo + col]) = v1;
        }
    }
}

// ---------------------------------------------------------------------------
// K5: exact fp32 router logits  g_L = x @ routerW^T (side stream).
// ---------------------------------------------------------------------------
__global__ __launch_bounds__(512) void router_kernel(
    const float* __restrict__ x, const float* __restrict__ routerW)
{
    extern __shared__ float rw[];               // [NE * DIM] = 128KB
    const int tid = threadIdx.x, lane = tid & 31, warp = tid >> 5;
    const int token = blockIdx.x * 16 + warp;

    for (int i = tid; i < NE * DIM / 4; i += 512)
        reinterpret_cast<float4*>(rw)[i] = reinterpret_cast<const float4*>(routerW)[i];
    __syncthreads();

    const float4* xr  = reinterpret_cast<const float4*>(x + (size_t)token * DIM);
    const float4* rwv = reinterpret_cast<const float4*>(rw);

    float acc[NE];
    #pragma unroll
    for (int e = 0; e < NE; e++) acc[e] = 0.f;

    #pragma unroll 4
    for (int t = 0; t < 32; t++) {
        int i4 = lane + 32 * t;
        float4 xv = __ldg(xr + i4);
        #pragma unroll
        for (int e = 0; e < NE; e++) {
            float4 w = rwv[e * (DIM / 4) + i4];
            acc[e] += xv.x * w.x + xv.y * w.y + xv.z * w.z + xv.w * w.w;
        }
    }
    #pragma unroll
    for (int e = 0; e < NE; e++)
        #pragma unroll
        for (int o = 16; o > 0; o >>= 1)
            acc[e] += __shfl_xor_sync(0xffffffffu, acc[e], o);

    if (lane == 0) {
        #pragma unroll
        for (int e = 0; e < NE; e++)
            g_L[(size_t)token * NE + e] = acc[e];
    }
}

// ---------------------------------------------------------------------------
// K6: finalize — reduce split-K partials, top-2 gates from g_L, head softmax,
// u -> Xh[:, 4096:] (permuted). 8 tokens / block, 256 threads.
// ---------------------------------------------------------------------------
__global__ __launch_bounds__(256) void finalize_kernel()
{
    __shared__ float sP[8][160];
    __shared__ float scoeff[8][24];

    const int tid = threadIdx.x, lane = tid & 31, warp = tid >> 5;
    const int token = blockIdx.x * 8 + warp;

    #pragma unroll
    for (int rep = 0; rep < 5; rep++) {
        int idx = lane + 32 * rep;
        float s = 0.f;
        #pragma unroll
        for (int sl = 0; sl < KSLICES; sl++)
            s += g_P4[((size_t)sl * N_TOK + token) * NWG + idx];
        sP[warp][idx] = s;
    }
    __syncwarp();

    if (lane == 0) {
        float acc[NE];
        #pragma unroll
        for (int e = 0; e < NE; e++) acc[e] = g_L[(size_t)token * NE + e];

        int i1 = 0;
        #pragma unroll
        for (int e = 1; e < NE; e++) if (acc[e] > acc[i1]) i1 = e;
        int i2 = (i1 == 0) ? 1 : 0;
        #pragma unroll
        for (int e = 0; e < NE; e++)
            if (e != i1 && acc[e] > acc[i2]) i2 = e;

        float ed = expf(acc[i2] - acc[i1]);
        float g1 = 1.f / (1.f + ed);
        float g2 = ed / (1.f + ed);

        #pragma unroll
        for (int q = 0; q < 24; q++) scoeff[warp][q] = 0.f;

        int   ids[2] = {i1, i2};
        float gs[2]  = {g1, g2};
        #pragma unroll
        for (int p = 0; p < 2; p++) {
            int e = ids[p];
            float h0 = sP[warp][128 + e * 3 + 0];
            float h1 = sP[warp][128 + e * 3 + 1];
            float h2 = sP[warp][128 + e * 3 + 2];
            float m  = fmaxf(h0, fmaxf(h1, h2));
            float x0 = expf(h0 - m), x1 = expf(h1 - m), x2 = expf(h2 - m);
            float inv = gs[p] * SCALE_F / (x0 + x1 + x2);
            scoeff[warp][e * 3 + 0] = x0 * inv;
            scoeff[warp][e * 3 + 1] = x1 * inv;
            scoeff[warp][e * 3 + 2] = x2 * inv;
        }
    }
    __syncwarp();

    #pragma unroll
    for (int rep = 0; rep < NU / 32; rep++) {
        int j = lane + 32 * rep;
        int e = j / 48;
        int jr = j - e * 48;
        int h = jr >> 4, r = jr & 15;
        float u = scoeff[warp][e * 3 + h] * sP[warp][e * 16 + r];
        g_Xh[(size_t)token * K_ALL + DIM + (j & ~31) + hperm32(j & 31)] =
            __float2half_rn(u);
    }
}

// ---------------------------------------------------------------------------
// host launch — R10 schedule + gather on the side stream + 1-wave prep GEMM.
// ---------------------------------------------------------------------------
extern "C" void kernel_launch(void* const* d_in, const int* in_sizes, int n_in,
                              void* d_out, int out_size) {
    const float* x       = (const float*)d_in[0];
    const float* baseW   = (const float*)d_in[1];
    const float* routerW = (const float*)d_in[2];
    const float* A       = (const float*)d_in[3];
    const float* B       = (const float*)d_in[4];
    const float* Rm      = (const float*)d_in[5];
    float* out = (float*)d_out;

    void *pXh = nullptr, *pWh = nullptr, *pWgh = nullptr, *pP4 = nullptr;
    cudaGetSymbolAddress(&pXh,  g_Xh);
    cudaGetSymbolAddress(&pWh,  g_Wh);
    cudaGetSymbolAddress(&pWgh, g_Wgh);
    cudaGetSymbolAddress(&pP4,  g_P4);

    static bool init_done = false;
    static cudaStream_t s1, s2;
    static cudaEvent_t evRoot, evG, evW, evL;
    if (!init_done) {
        cudaFuncSetAttribute(mma_gemm_kernel,
                             cudaFuncAttributeMaxDynamicSharedMemorySize, SMEM_GEMM);
        cudaFuncSetAttribute(router_kernel,
                             cudaFuncAttributeMaxDynamicSharedMemorySize,
                             NE * DIM * sizeof(float));
        cudaStreamCreateWithFlags(&s1, cudaStreamNonBlocking);
        cudaStreamCreateWithFlags(&s2, cudaStreamNonBlocking);
        cudaEventCreateWithFlags(&evRoot, cudaEventDisableTiming);
        cudaEventCreateWithFlags(&evG,    cudaEventDisableTiming);
        cudaEventCreateWithFlags(&evW,    cudaEventDisableTiming);
        cudaEventCreateWithFlags(&evL,    cudaEventDisableTiming);
        init_done = true;
    }

    // fork side streams off the main stream
    cudaEventRecord(evRoot, 0);
    cudaStreamWaitEvent(s1, evRoot, 0);
    cudaStreamWaitEvent(s2, evRoot, 0);

    // s1: prep weights first (needed by prep GEMM), then W transpose
    gather_wg_kernel<<<(NWG * 128) / 256, 256, 0, s1>>>(A, Rm);
    cudaEventRecord(evG, s1);
    transpose_w_kernel<<<dim3(K_ALL / 128, OUT_DIM / 64), 256, 0, s1>>>(baseW, B);
    cudaEventRecord(evW, s1);

    // s2: exact fp32 router logits (needed only by finalize)
    router_kernel<<<N_TOK / 16, 512, NE * DIM * sizeof(float), s2>>>(x, routerW);
    cudaEventRecord(evL, s2);

    // main stream: x rounding -> prep GEMM (single wave, KSLICES=4)
    round_x_kernel<<<(N_TOK * 128) / 256, 256>>>(x);
    cudaStreamWaitEvent(0, evG, 0);
    {
        int stages = DIM / BKH / KSLICES;                 // 16
        size_t slice_k = (size_t)stages * BKH;            // 1024 halves
        mma_gemm_kernel<<<dim3(NWG / BN, N_TOK / BM, KSLICES), NTHR, SMEM_GEMM>>>(
            (const __half*)pXh, K_ALL, (const __half*)pWgh, DIM,
            (float*)pP4, NWG, stages, slice_k, (size_t)N_TOK * NWG);
    }

    // finalize needs router logits
    cudaStreamWaitEvent(0, evL, 0);
    finalize_kernel<<<N_TOK / 8, 256>>>();

    // main GEMM needs Wh
    cudaStreamWaitEvent(0, evW, 0);
    mma_gemm_kernel<<<dim3(OUT_DIM / BN, N_TOK / BM, 1), NTHR, SMEM_GEMM>>>(
        (const __half*)pXh, K_ALL, (const __half*)pWh, K_ALL,
        out, OUT_DIM, K_ALL / BKH, 0, 0);
}

// round 14
// speedup vs baseline: 1.0812x; 1.0121x over previous
#include <cuda_runtime.h>
#include <cuda_fp16.h>
#include <cstdint>

// ---------------------------------------------------------------------------
// Problem constants
// ---------------------------------------------------------------------------
#define N_TOK   4096
#define DIM     4096
#define OUT_DIM 4096
#define NE      8
#define NH      3
#define NR      16
#define NU      384
#define K_ALL   (DIM + NU)     // 4480
#define SCALE_F 2.0f
#define NWG     256            // padded prep-weight rows
#define KSLICES 4              // prep GEMM split-K: 256 CTAs = one wave

// Scratch (static). Rows are K-major fp16 with a permutation inside each
// 32-element k-group: pos(k) = ((k>>1)&3)*8 + ((k>>3)&3)*2 + (k&1)
__device__ __half g_Xh[(size_t)N_TOK * K_ALL];           // [N][4480] rn(x) | rn(u)
__device__ __half g_Wh[(size_t)OUT_DIM * K_ALL];         // [O][4480] rn([baseW;Bfl]^T)
__device__ __half g_Wgh[(size_t)NWG * DIM];              // [256][4096] gathered A,R
__device__ float  g_P4[(size_t)KSLICES * N_TOK * NWG];   // split-K partials (fp32)
__device__ float  g_L [(size_t)N_TOK * NE];              // exact fp32 router logits

__device__ __forceinline__ int hperm32(int k) {
    return ((k >> 1) & 3) * 8 + ((k >> 3) & 3) * 2 + (k & 1);
}

// ---------------------------------------------------------------------------
// K1: Xh[:, 0:4096] = rn_f16(x), permuted. smem-staged: coalesced float4
// global reads, skew-33 scalar STS (conflict-free), static-indexed convert
// (registers), 16B uint4 global writes. 2 token-rows per block.
// ---------------------------------------------------------------------------
__global__ __launch_bounds__(256) void round_x_kernel(const float* __restrict__ x) {
    __shared__ float sx[2 * 128 * 33];            // 33 KB, skewed groups
    const int tid = threadIdx.x;
    const size_t row0 = (size_t)blockIdx.x * 2;

    #pragma unroll
    for (int i = 0; i < 8; i++) {
        int idx = i * 256 + tid;                  // 0..2047 float4 slot
        int r = idx >> 10;                        // row 0/1
        int c = idx & 1023;                       // float4 within row
        float4 v = reinterpret_cast<const float4*>(x + (row0 + r) * DIM)[c];
        int grp = c >> 3;                         // 32-float group
        int j0  = (c & 7) * 4;
        float* d = sx + (r * 128 + grp) * 33 + j0;
        d[0] = v.x; d[1] = v.y; d[2] = v.z; d[3] = v.w;
    }
    __syncthreads();

    const int r   = tid >> 7;                     // 0..1
    const int grp = tid & 127;
    const float* src = sx + (r * 128 + grp) * 33;
    __align__(16) __half tmp[32];
    #pragma unroll
    for (int j = 0; j < 32; j++)                  // static indices -> registers
        tmp[hperm32(j)] = __float2half_rn(src[j]);
    uint4* dst = reinterpret_cast<uint4*>(g_Xh + (row0 + r) * K_ALL + grp * 32);
    const uint4* tp = reinterpret_cast<const uint4*>(tmp);
    #pragma unroll
    for (int q = 0; q < 4; q++) dst[q] = tp[q];
}

// ---------------------------------------------------------------------------
// K2: Wh[n][perm(k)] = rn_f16([baseW;Bfl]^T). Tile K=128 x N=64, smem-staged.
// ---------------------------------------------------------------------------
__global__ __launch_bounds__(256) void transpose_w_kernel(
    const float* __restrict__ baseW, const float* __restrict__ Bfl) {
    __shared__ float st[128][66];
    const int tid = threadIdx.x;
    const int kb = blockIdx.x * 128, nb = blockIdx.y * 64;

    const bool isB = (kb >= DIM);
    const float* src = isB ? (Bfl + (size_t)(kb - DIM) * OUT_DIM + nb)
                           : (baseW + (size_t)kb * OUT_DIM + nb);
    #pragma unroll
    for (int i = 0; i < 8; i++) {
        int idx = i * 256 + tid;            // 0..2047
        int k = idx >> 4, q = idx & 15;
        float4 v = *reinterpret_cast<const float4*>(src + (size_t)k * OUT_DIM + q * 4);
        st[k][q * 4 + 0] = v.x;
        st[k][q * 4 + 1] = v.y;
        st[k][q * 4 + 2] = v.z;
        st[k][q * 4 + 3] = v.w;
    }
    __syncthreads();

    const int n = tid & 63;
    const int c = tid >> 6;                  // 0..3
    __align__(16) __half tmp[32];
    #pragma unroll
    for (int j = 0; j < 32; j++)
        tmp[hperm32(j)] = __float2half_rn(st[c * 32 + j][n]);
    uint4* dst = reinterpret_cast<uint4*>(
        g_Wh + (size_t)(nb + n) * K_ALL + kb + c * 32);
    const uint4* tp = reinterpret_cast<const uint4*>(tmp);
    #pragma unroll
    for (int q = 0; q < 4; q++) dst[q] = tp[q];
}

// ---------------------------------------------------------------------------
// K3: gather Wgh (permuted): rows 0..127 = A[e][:,r], 128..151 = Rm[e][:,h].
// ---------------------------------------------------------------------------
__global__ __launch_bounds__(256) void gather_wg_kernel(
    const float* __restrict__ A, const float* __restrict__ Rm) {
    int idx = blockIdx.x * 256 + threadIdx.x;   // NWG * 128 total
    int j = idx >> 7, gd = idx & 127;
    int d0 = gd * 32;
    __align__(16) __half tmp[32];
    if (j < 128) {
        int e = j >> 4, rr = j & 15;
        const float* base = A + (size_t)e * DIM * NR + rr;
        #pragma unroll
        for (int d = 0; d < 32; d++)
            tmp[hperm32(d)] = __float2half_rn(base[(size_t)(d0 + d) * NR]);
    } else if (j < 152) {
        int jj = j - 128, e = jj / 3, h = jj - 3 * e;
        const float* base = Rm + (size_t)e * DIM * NH + h;
        #pragma unroll
        for (int d = 0; d < 32; d++)
            tmp[hperm32(d)] = __float2half_rn(base[(size_t)(d0 + d) * NH]);
    } else {
        #pragma unroll
        for (int d = 0; d < 32; d++) tmp[d] = __float2half_rn(0.f);
    }
    uint4* dst = reinterpret_cast<uint4*>(g_Wgh + (size_t)j * DIM + d0);
    const uint4* tp = reinterpret_cast<const uint4*>(tmp);
    #pragma unroll
    for (int q = 0; q < 4; q++) dst[q] = tp[q];
}

// ---------------------------------------------------------------------------
// K4: FP16 tensor GEMM (fp32 accum)  out = A[M][lda] @ B[N][ldb]^T.
// 128x128 CTA, 2x2 warps (64x64), BK=64, 3-stage cp.async, 2 CTAs/SM.
// ---------------------------------------------------------------------------
#define BM 128
#define BN 128
#define BKH 64
#define NSTAGE 3
#define ASTG (BM * 128)        // 16 KB
#define BSTG (BN * 128)        // 16 KB
#define SMEM_GEMM (NSTAGE * (ASTG + BSTG))   // 96 KB
#define NTHR 128

__device__ __forceinline__ void cp16(uint32_t daddr, const void* gptr) {
    asm volatile("cp.async.cg.shared.global [%0], [%1], 16;"
                 :: "r"(daddr), "l"(gptr) : "memory");
}
__device__ __forceinline__ uint4 lds128(uint32_t a) {
    uint4 v;
    asm volatile("ld.shared.v4.b32 {%0,%1,%2,%3}, [%4];"
                 : "=r"(v.x), "=r"(v.y), "=r"(v.z), "=r"(v.w) : "r"(a));
    return v;
}
__device__ __forceinline__ uint32_t smem_u32(const void* p) {
    uint32_t a;
    asm("{ .reg .u64 t; cvta.to.shared.u64 t, %1; cvt.u32.u64 %0, t; }" : "=r"(a) : "l"(p));
    return a;
}
__device__ __forceinline__ uint32_t swz(uint32_t v) {
    return ((v & 1u) << 2) | (v >> 1);
}
__device__ __forceinline__ void mma16(float* c, uint32_t a0, uint32_t a1,
                                      uint32_t a2, uint32_t a3,
                                      uint32_t b0, uint32_t b1) {
    asm("mma.sync.aligned.m16n8k16.row.col.f32.f16.f16.f32 "
        "{%0,%1,%2,%3}, {%4,%5,%6,%7}, {%8,%9}, {%0,%1,%2,%3};\n"
        : "+f"(c[0]), "+f"(c[1]), "+f"(c[2]), "+f"(c[3])
        : "r"(a0), "r"(a1), "r"(a2), "r"(a3), "r"(b0), "r"(b1));
}

__global__ __launch_bounds__(NTHR, 2) void mma_gemm_kernel(
    const __half* __restrict__ Ag, int lda,
    const __half* __restrict__ Bg, int ldb,
    float* __restrict__ out, int ldo, int ksteps,
    size_t slice_k, size_t out_slice)
{
    extern __shared__ __align__(1024) char sm[];
    const uint32_t smuA = smem_u32(sm);
    const uint32_t smuB = smuA + NSTAGE * ASTG;

    Ag  += (size_t)blockIdx.z * slice_k;
    Bg  += (size_t)blockIdx.z * slice_k;
    out += (size_t)blockIdx.z * out_slice;

    const int tid = threadIdx.x, lane = tid & 31, warp = tid >> 5;
    const int wm = warp & 1, wn = warp >> 1;
    const int g = lane >> 2, tg = lane & 3;
    const int m0 = blockIdx.y * BM, n0 = blockIdx.x * BN;

    const int lrow = tid >> 3;
    const int lkq  = tid & 7;
    const uint32_t sgr = (lkq ^ swz(lrow & 7)) * 16;

    float c[4][8][4];
    #pragma unroll
    for (int i = 0; i < 4; i++)
        #pragma unroll
        for (int j = 0; j < 8; j++)
            #pragma unroll
            for (int k = 0; k < 4; k++) c[i][j][k] = 0.f;

    auto issue = [&](int kt, int s) {
        const __half* ab = Ag + (size_t)(m0 + lrow) * lda + (size_t)kt * BKH + lkq * 8;
        const __half* bb = Bg + (size_t)(n0 + lrow) * ldb + (size_t)kt * BKH + lkq * 8;
        #pragma unroll
        for (int i = 0; i < 8; i++)
            cp16(smuA + s * ASTG + (lrow + 16 * i) * 128 + sgr,
                 ab + (size_t)(16 * i) * lda);
        #pragma unroll
        for (int i = 0; i < 8; i++)
            cp16(smuB + s * BSTG + (lrow + 16 * i) * 128 + sgr,
                 bb + (size_t)(16 * i) * ldb);
    };

    #pragma unroll
    for (int s = 0; s < NSTAGE - 1; s++) {
        issue(s, s);
        asm volatile("cp.async.commit_group;" ::: "memory");
    }

    const uint32_t fsw = swz((uint32_t)g) * 16;

    for (int kt = 0; kt < ksteps; kt++) {
        const int cur = kt % NSTAGE;
        asm volatile("cp.async.wait_group %0;" :: "n"(NSTAGE - 2) : "memory");
        __syncthreads();

        int nk = kt + NSTAGE - 1;
        if (nk < ksteps) issue(nk, nk % NSTAGE);
        asm volatile("cp.async.commit_group;" ::: "memory");

        const uint32_t sA = smuA + cur * ASTG + (wm * 64 + g) * 128;
        const uint32_t sB = smuB + cur * BSTG + (wn * 64 + g) * 128;

        #pragma unroll
        for (int chk = 0; chk < 2; chk++) {
            const uint32_t goff = ((chk * 4 + tg) * 16) ^ fsw;
            uint4 alo[4], ahi[4], bv[8];
            #pragma unroll
            for (int im = 0; im < 4; im++) {
                uint32_t ra = sA + im * 16 * 128 + goff;
                alo[im] = lds128(ra);
                ahi[im] = lds128(ra + 8 * 128);
            }
            #pragma unroll
            for (int in = 0; in < 8; in++)
                bv[in] = lds128(sB + in * 8 * 128 + goff);

            #pragma unroll
            for (int im = 0; im < 4; im++)
                #pragma unroll
                for (int in = 0; in < 8; in++) {
                    mma16(c[im][in], alo[im].x, ahi[im].x, alo[im].y, ahi[im].y,
                          bv[in].x, bv[in].y);
                    mma16(c[im][in], alo[im].z, ahi[im].z, alo[im].w, ahi[im].w,
                          bv[in].z, bv[in].w);
                }
        }
    }

    #pragma unroll
    for (int im = 0; im < 4; im++) {
        int row = m0 + wm * 64 + im * 16 + g;
        #pragma unroll
        for (int in = 0; in < 8; in++) {
            int col = n0 + wn * 64 + in * 8 + 2 * tg;
            float2 v0 = make_float2(c[im][in][0], c[im][in][1]);
            float2 v1 = make_float2(c[im][in][2], c[im][in][3]);
            *reinterpret_cast<float2*>(&out[(size_t)row * ldo + col])       = v0;
            *reinterpret_cast<float2*>(&out[(size_t)(row + 8) * ldo + col]) = v1;
        }
    }
}

// ---------------------------------------------------------------------------
// K5: exact fp32 router logits  g_L = x @ routerW^T (side stream).
// ---------------------------------------------------------------------------
__global__ __launch_bounds__(512) void router_kernel(
    const float* __restrict__ x, const float* __restrict__ routerW)
{
    extern __shared__ float rw[];               // [NE * DIM] = 128KB
    const int tid = threadIdx.x, lane = tid & 31, warp = tid >> 5;
    const int token = blockIdx.x * 16 + warp;

    for (int i = tid; i < NE * DIM / 4; i += 512)
        reinterpret_cast<float4*>(rw)[i] = reinterpret_cast<const float4*>(routerW)[i];
    __syncthreads();

    const float4* xr  = reinterpret_cast<const float4*>(x + (size_t)token * DIM);
    const float4* rwv = reinterpret_cast<const float4*>(rw);

    float acc[NE];
    #pragma unroll
    for (int e = 0; e < NE; e++) acc[e] = 0.f;

    #pragma unroll 4
    for (int t = 0; t < 32; t++) {
        int i4 = lane + 32 * t;
        float4 xv = __ldg(xr + i4);
        #pragma unroll
        for (int e = 0; e < NE; e++) {
            float4 w = rwv[e * (DIM / 4) + i4];
            acc[e] += xv.x * w.x + xv.y * w.y + xv.z * w.z + xv.w * w.w;
        }
    }
    #pragma unroll
    for (int e = 0; e < NE; e++)
        #pragma unroll
        for (int o = 16; o > 0; o >>= 1)
            acc[e] += __shfl_xor_sync(0xffffffffu, acc[e], o);

    if (lane == 0) {
        #pragma unroll
        for (int e = 0; e < NE; e++)
            g_L[(size_t)token * NE + e] = acc[e];
    }
}

// ---------------------------------------------------------------------------
// K6: finalize — reduce split-K partials, top-2 gates from g_L, head softmax,
// u -> Xh[:, 4096:] (permuted). 8 tokens / block, 256 threads.
// ---------------------------------------------------------------------------
__global__ __launch_bounds__(256) void finalize_kernel()
{
    __shared__ float sP[8][160];
    __shared__ float scoeff[8][24];

    const int tid = threadIdx.x, lane = tid & 31, warp = tid >> 5;
    const int token = blockIdx.x * 8 + warp;

    #pragma unroll
    for (int rep = 0; rep < 5; rep++) {
        int idx = lane + 32 * rep;
        float s = 0.f;
        #pragma unroll
        for (int sl = 0; sl < KSLICES; sl++)
            s += g_P4[((size_t)sl * N_TOK + token) * NWG + idx];
        sP[warp][idx] = s;
    }
    __syncwarp();

    if (lane == 0) {
        float acc[NE];
        #pragma unroll
        for (int e = 0; e < NE; e++) acc[e] = g_L[(size_t)token * NE + e];

        int i1 = 0;
        #pragma unroll
        for (int e = 1; e < NE; e++) if (acc[e] > acc[i1]) i1 = e;
        int i2 = (i1 == 0) ? 1 : 0;
        #pragma unroll
        for (int e = 0; e < NE; e++)
            if (e != i1 && acc[e] > acc[i2]) i2 = e;

        float ed = expf(acc[i2] - acc[i1]);
        float g1 = 1.f / (1.f + ed);
        float g2 = ed / (1.f + ed);

        #pragma unroll
        for (int q = 0; q < 24; q++) scoeff[warp][q] = 0.f;

        int   ids[2] = {i1, i2};
        float gs[2]  = {g1, g2};
        #pragma unroll
        for (int p = 0; p < 2; p++) {
            int e = ids[p];
            float h0 = sP[warp][128 + e * 3 + 0];
            float h1 = sP[warp][128 + e * 3 + 1];
            float h2 = sP[warp][128 + e * 3 + 2];
            float m  = fmaxf(h0, fmaxf(h1, h2));
            float x0 = expf(h0 - m), x1 = expf(h1 - m), x2 = expf(h2 - m);
            float inv = gs[p] * SCALE_F / (x0 + x1 + x2);
            scoeff[warp][e * 3 + 0] = x0 * inv;
            scoeff[warp][e * 3 + 1] = x1 * inv;
            scoeff[warp][e * 3 + 2] = x2 * inv;
        }
    }
    __syncwarp();

    #pragma unroll
    for (int rep = 0; rep < NU / 32; rep++) {
        int j = lane + 32 * rep;
        int e = j / 48;
        int jr = j - e * 48;
        int h = jr >> 4, r = jr & 15;
        float u = scoeff[warp][e * 3 + h] * sP[warp][e * 16 + r];
        g_Xh[(size_t)token * K_ALL + DIM + (j & ~31) + hperm32(j & 31)] =
            __float2half_rn(u);
    }
}

// ---------------------------------------------------------------------------
// host launch — R13 schedule (best known): gather+transpose on s1, router on
// s2, round_x -> 1-wave prep GEMM -> finalize -> main GEMM on main stream.
// ---------------------------------------------------------------------------
extern "C" void kernel_launch(void* const* d_in, const int* in_sizes, int n_in,
                              void* d_out, int out_size) {
    const float* x       = (const float*)d_in[0];
    const float* baseW   = (const float*)d_in[1];
    const float* routerW = (const float*)d_in[2];
    const float* A       = (const float*)d_in[3];
    const float* B       = (const float*)d_in[4];
    const float* Rm      = (const float*)d_in[5];
    float* out = (float*)d_out;

    void *pXh = nullptr, *pWh = nullptr, *pWgh = nullptr, *pP4 = nullptr;
    cudaGetSymbolAddress(&pXh,  g_Xh);
    cudaGetSymbolAddress(&pWh,  g_Wh);
    cudaGetSymbolAddress(&pWgh, g_Wgh);
    cudaGetSymbolAddress(&pP4,  g_P4);

    static bool init_done = false;
    static cudaStream_t s1, s2;
    static cudaEvent_t evRoot, evG, evW, evL;
    if (!init_done) {
        cudaFuncSetAttribute(mma_gemm_kernel,
                             cudaFuncAttributeMaxDynamicSharedMemorySize, SMEM_GEMM);
        cudaFuncSetAttribute(router_kernel,
                             cudaFuncAttributeMaxDynamicSharedMemorySize,
                             NE * DIM * sizeof(float));
        cudaStreamCreateWithFlags(&s1, cudaStreamNonBlocking);
        cudaStreamCreateWithFlags(&s2, cudaStreamNonBlocking);
        cudaEventCreateWithFlags(&evRoot, cudaEventDisableTiming);
        cudaEventCreateWithFlags(&evG,    cudaEventDisableTiming);
        cudaEventCreateWithFlags(&evW,    cudaEventDisableTiming);
        cudaEventCreateWithFlags(&evL,    cudaEventDisableTiming);
        init_done = true;
    }

    // fork side streams off the main stream
    cudaEventRecord(evRoot, 0);
    cudaStreamWaitEvent(s1, evRoot, 0);
    cudaStreamWaitEvent(s2, evRoot, 0);

    // s1: prep weights first (needed by prep GEMM), then W transpose
    gather_wg_kernel<<<(NWG * 128) / 256, 256, 0, s1>>>(A, Rm);
    cudaEventRecord(evG, s1);
    transpose_w_kernel<<<dim3(K_ALL / 128, OUT_DIM / 64), 256, 0, s1>>>(baseW, B);
    cudaEventRecord(evW, s1);

    // s2: exact fp32 router logits (needed only by finalize)
    router_kernel<<<N_TOK / 16, 512, NE * DIM * sizeof(float), s2>>>(x, routerW);
    cudaEventRecord(evL, s2);

    // main stream: x rounding -> prep GEMM (single wave, KSLICES=4)
    round_x_kernel<<<N_TOK / 2, 256>>>(x);
    cudaStreamWaitEvent(0, evG, 0);
    {
        int stages = DIM / BKH / KSLICES;                 // 16
        size_t slice_k = (size_t)stages * BKH;            // 1024 halves
        mma_gemm_kernel<<<dim3(NWG / BN, N_TOK / BM, KSLICES), NTHR, SMEM_GEMM>>>(
            (const __half*)pXh, K_ALL, (const __half*)pWgh, DIM,
            (float*)pP4, NWG, stages, slice_k, (size_t)N_TOK * NWG);
    }

    // finalize needs router logits
    cudaStreamWaitEvent(0, evL, 0);
    finalize_kernel<<<N_TOK / 8, 256>>>();

    // main GEMM needs Wh
    cudaStreamWaitEvent(0, evW, 0);
    mma_gemm_kernel<<<dim3(OUT_DIM / BN, N_TOK / BM, 1), NTHR, SMEM_GEMM>>>(
        (const __half*)pXh, K_ALL, (const __half*)pWh, K_ALL,
        out, OUT_DIM, K_ALL / BKH, 0, 0);
}